// round 6
// baseline (speedup 1.0000x reference)
#include <cuda_runtime.h>
#include <math.h>

#define NSAMP 8192
#define SEQ   (NSAMP*3)      /* 24576 sequential LSTM steps */
#define E     1024
#define HH    1024
#define G4    4096
#define RULED 32
#define OUTD  2
#define NCTA  128
#define POISON 0xFFFFFFFFu   /* NaN bit pattern; h = o*tanh(c) in (-1,1) never matches */

/* Static device scratch — 256B-aligned so vector (128-bit) accesses are legal */
__device__ __align__(256) float g_X [(size_t)SEQ * E];        /* ~100 MB */
__device__ __align__(256) float g_Gx[(size_t)SEQ * G4];       /* ~403 MB */
__device__ __align__(256) float g_h [(size_t)(SEQ + 1) * HH]; /* ~100 MB */

/* ---- packed f32x2 helpers (sm_103a FFMA2 is PTX-only) ------------- */
__device__ __forceinline__ unsigned long long pk2(float x, float y) {
    unsigned long long r;
    asm("mov.b64 %0,{%1,%2};" : "=l"(r) : "f"(x), "f"(y));
    return r;
}
__device__ __forceinline__ unsigned long long fma2(
    unsigned long long a, unsigned long long b, unsigned long long c) {
    unsigned long long d;
    asm("fma.rn.f32x2 %0,%1,%2,%3;" : "=l"(d) : "l"(a), "l"(b), "l"(c));
    return d;
}
__device__ __forceinline__ float sum2(unsigned long long v) {
    float x, y;
    asm("mov.b64 {%0,%1},%2;" : "=f"(x), "=f"(y) : "l"(v));
    return x + y;
}

/* ------------------------------------------------------------------ */
/* Init: h row 0 = 0.0f, rows 1..SEQ = NaN poison (data IS the flag). */
__global__ __launch_bounds__(256) void poison_k()
{
    const size_t total = (size_t)(SEQ + 1) * HH;
    unsigned* p = (unsigned*)g_h;
    for (size_t i = (size_t)blockIdx.x * 256 + threadIdx.x; i < total;
         i += (size_t)gridDim.x * 256)
        p[i] = (i < HH) ? 0u : POISON;
}

/* ------------------------------------------------------------------ */
/* Build X: row 3n = rules@W_rule + b_rule, rows 3n+1/2 = face gather */
__global__ __launch_bounds__(256) void build_x_k(
    const float* __restrict__ rules, const int* __restrict__ id1,
    const int* __restrict__ id2, const float* __restrict__ W_rule,
    const float* __restrict__ b_rule, const float* __restrict__ face)
{
    int s = blockIdx.x;
    int n = s / 3, t = s - n * 3;
    float* dst = g_X + (size_t)s * E;
    if (t == 0) {
        __shared__ float r[RULED];
        if (threadIdx.x < RULED) r[threadIdx.x] = rules[n * RULED + threadIdx.x];
        __syncthreads();
        for (int e = threadIdx.x; e < E; e += 256) {
            float acc = b_rule[e];
            #pragma unroll
            for (int k = 0; k < RULED; ++k) acc += r[k] * W_rule[k * E + e];
            dst[e] = acc;
        }
    } else {
        int id = (t == 1 ? id1 : id2)[n];
        const float4* src = (const float4*)(face + (size_t)id * E);
        float4* d4 = (float4*)dst;
        for (int i = threadIdx.x; i < E / 4; i += 256) d4[i] = src[i];
    }
}

/* ------------------------------------------------------------------ */
/* Gx[s][r] = dot(X[s,:], W_ih[r,:]) + b_ih[r] + b_hh[r]  (C = A B^T) */
#define BM 128
#define BN 128
#define BK 16
__global__ __launch_bounds__(256) void gemm_gx_k(
    const float* __restrict__ B,          /* W_ih [4096][1024] */
    const float* __restrict__ bih, const float* __restrict__ bhh)
{
    __shared__ float As[BK][BM + 4];
    __shared__ float Bs[BK][BN + 4];
    const int bm = blockIdx.y * BM;
    const int bn = blockIdx.x * BN;
    const int tid = threadIdx.x;
    const int ty = tid >> 4, tx = tid & 15;
    float acc[8][8] = {};
    const float* A = g_X;

    for (int k0 = 0; k0 < E; k0 += BK) {
        #pragma unroll
        for (int v = 0; v < 2; ++v) {
            int f4  = tid * 2 + v;
            int row = f4 >> 2;
            int kq  = f4 & 3;
            float4 a = *(const float4*)(A + (size_t)(bm + row) * E + k0 + kq * 4);
            As[kq*4+0][row] = a.x; As[kq*4+1][row] = a.y;
            As[kq*4+2][row] = a.z; As[kq*4+3][row] = a.w;
            float4 b = *(const float4*)(B + (size_t)(bn + row) * E + k0 + kq * 4);
            Bs[kq*4+0][row] = b.x; Bs[kq*4+1][row] = b.y;
            Bs[kq*4+2][row] = b.z; Bs[kq*4+3][row] = b.w;
        }
        __syncthreads();
        #pragma unroll
        for (int k = 0; k < BK; ++k) {
            float ar[8], br[8];
            #pragma unroll
            for (int i = 0; i < 8; ++i) ar[i] = As[k][ty*8 + i];
            #pragma unroll
            for (int i = 0; i < 8; ++i) br[i] = Bs[k][tx*8 + i];
            #pragma unroll
            for (int i = 0; i < 8; ++i)
                #pragma unroll
                for (int j = 0; j < 8; ++j) acc[i][j] += ar[i] * br[j];
        }
        __syncthreads();
    }
    #pragma unroll
    for (int i = 0; i < 8; ++i) {
        size_t row = (size_t)(bm + ty*8 + i);
        #pragma unroll
        for (int j = 0; j < 8; ++j) {
            int col = bn + tx*8 + j;
            g_Gx[row * G4 + col] = acc[i][j] + bih[col] + bhh[col];
        }
    }
}

/* ------------------------------------------------------------------ */
/* Persistent sequential LSTM — barrier-free, smem-free step.         */
/* 128 CTAs x 256 threads. Warp w of CTA b owns h[j], j = b*8 + w.    */
/* Thread (warp,lane) covers k = 128*i + 4*lane + r  (i<8, r<4).      */
/* h row is read directly from L2 as 8 float4 chunks, each chunk      */
/* individually poison-polled (data-as-flag, per-chunk, no barrier).  */
__global__ __launch_bounds__(256, 1) void lstm_seq_k(const float* __restrict__ Whh)
{
    const int b    = blockIdx.x;
    const int tid  = threadIdx.x;
    const int warp = tid >> 5;
    const int lane = tid & 31;
    const int j    = b * 8 + warp;

    /* Pre-packed f32x2 weights: w2[q][i][p] covers k = 128*i+4*lane+2p.. */
    unsigned long long w2[4][8][2];
    #pragma unroll
    for (int q = 0; q < 4; ++q) {
        const float* wr = Whh + (size_t)(q * HH + j) * HH;
        #pragma unroll
        for (int i = 0; i < 8; ++i) {
            float4 wf = *(const float4*)(wr + i * 128 + lane * 4);
            w2[q][i][0] = pk2(wf.x, wf.y);
            w2[q][i][1] = pk2(wf.z, wf.w);
        }
    }

    float c = 0.0f;

    for (int t = 0; t < SEQ; ++t) {
        /* gate-bias prefetch (independent of h; overlaps the h polls) */
        const float* gx = g_Gx + (size_t)t * G4 + j;
        float gq0 = __ldg(gx);
        float gq1 = __ldg(gx + HH);
        float gq2 = __ldg(gx + 2 * HH);
        float gq3 = __ldg(gx + 3 * HH);

        /* batched h loads (MLP=8), then per-chunk poison re-poll */
        const float* hrow = g_h + (size_t)t * HH;
        float4 hv[8];
        #pragma unroll
        for (int i = 0; i < 8; ++i)
            hv[i] = __ldcg((const float4*)(hrow + i * 128 + lane * 4));
        #pragma unroll
        for (int i = 0; i < 8; ++i) {
            while (__float_as_uint(hv[i].x) == POISON ||
                   __float_as_uint(hv[i].y) == POISON ||
                   __float_as_uint(hv[i].z) == POISON ||
                   __float_as_uint(hv[i].w) == POISON) {
                volatile const float* p = hrow + i * 128 + lane * 4;
                hv[i].x = p[0]; hv[i].y = p[1]; hv[i].z = p[2]; hv[i].w = p[3];
            }
        }

        /* packed dot products: 4 gates x 8 chunks x 2 f32x2-FMA */
        unsigned long long acc0 = 0ull, acc1 = 0ull, acc2 = 0ull, acc3 = 0ull;
        #pragma unroll
        for (int i = 0; i < 8; ++i) {
            unsigned long long h01 = pk2(hv[i].x, hv[i].y);
            unsigned long long h23 = pk2(hv[i].z, hv[i].w);
            acc0 = fma2(w2[0][i][0], h01, acc0);
            acc1 = fma2(w2[1][i][0], h01, acc1);
            acc2 = fma2(w2[2][i][0], h01, acc2);
            acc3 = fma2(w2[3][i][0], h01, acc3);
            acc0 = fma2(w2[0][i][1], h23, acc0);
            acc1 = fma2(w2[1][i][1], h23, acc1);
            acc2 = fma2(w2[2][i][1], h23, acc2);
            acc3 = fma2(w2[3][i][1], h23, acc3);
        }
        float a0 = sum2(acc0), a1 = sum2(acc1), a2 = sum2(acc2), a3 = sum2(acc3);

        /* butterfly: afterwards every lane holds all 4 full sums */
        #pragma unroll
        for (int off = 16; off; off >>= 1) {
            a0 += __shfl_xor_sync(0xffffffffu, a0, off);
            a1 += __shfl_xor_sync(0xffffffffu, a1, off);
            a2 += __shfl_xor_sync(0xffffffffu, a2, off);
            a3 += __shfl_xor_sync(0xffffffffu, a3, off);
        }

        /* all lanes compute activations redundantly (no broadcasts)   */
        /* sigmoid(x) = 0.5 + 0.5*tanh(x/2)  -> MUFU.TANH              */
        float ig = 0.5f + 0.5f * __tanhf(0.5f * (a0 + gq0));
        float fg = 0.5f + 0.5f * __tanhf(0.5f * (a1 + gq1));
        float gg = __tanhf(a2 + gq2);
        float og = 0.5f + 0.5f * __tanhf(0.5f * (a3 + gq3));

        c = fg * c + ig * gg;
        float hn = og * __tanhf(c);

        /* publish h(t+1): the stored value is itself the ready flag */
        if (lane == 0)
            __stcg(g_h + (size_t)(t + 1) * HH + j, hn);
    }
}

/* ------------------------------------------------------------------ */
/* out[n] = h(after sample n) @ W_out + b_out                          */
__global__ __launch_bounds__(256) void out_k(
    const float* __restrict__ Wout, const float* __restrict__ bout,
    float* __restrict__ out)
{
    int n = blockIdx.x;
    const float* h = g_h + (size_t)(3 * n + 3) * HH;
    float p0 = 0.f, p1 = 0.f;
    for (int jj = threadIdx.x; jj < HH; jj += 256) {
        float hv = h[jj];
        p0 += hv * Wout[jj * 2 + 0];
        p1 += hv * Wout[jj * 2 + 1];
    }
    __shared__ float s0[256], s1[256];
    s0[threadIdx.x] = p0; s1[threadIdx.x] = p1;
    __syncthreads();
    for (int st = 128; st; st >>= 1) {
        if (threadIdx.x < st) {
            s0[threadIdx.x] += s0[threadIdx.x + st];
            s1[threadIdx.x] += s1[threadIdx.x + st];
        }
        __syncthreads();
    }
    if (threadIdx.x == 0) {
        out[n * 2 + 0] = s0[0] + bout[0];
        out[n * 2 + 1] = s1[0] + bout[1];
    }
}

/* ------------------------------------------------------------------ */
extern "C" void kernel_launch(void* const* d_in, const int* in_sizes, int n_in,
                              void* d_out, int out_size)
{
    const float* rules  = (const float*)d_in[0];
    const int*   id1    = (const int*)  d_in[1];
    const int*   id2    = (const int*)  d_in[2];
    const float* W_rule = (const float*)d_in[3];
    const float* b_rule = (const float*)d_in[4];
    const float* face   = (const float*)d_in[5];
    const float* W_ih   = (const float*)d_in[6];
    const float* W_hh   = (const float*)d_in[7];
    const float* b_ih   = (const float*)d_in[8];
    const float* b_hh   = (const float*)d_in[9];
    const float* W_out  = (const float*)d_in[10];
    const float* b_out  = (const float*)d_in[11];
    float* out = (float*)d_out;

    poison_k<<<2048, 256>>>();
    build_x_k<<<SEQ, 256>>>(rules, id1, id2, W_rule, b_rule, face);
    gemm_gx_k<<<dim3(G4 / BN, SEQ / BM), 256>>>(W_ih, b_ih, b_hh);
    lstm_seq_k<<<NCTA, 256>>>(W_hh);
    out_k<<<NSAMP, 256>>>(W_out, b_out, out);
}

// round 7
// speedup vs baseline: 8.5806x; 8.5806x over previous
#include <cuda_runtime.h>
#include <math.h>

#define NSAMP 8192
#define SEQ   (NSAMP*3)      /* 24576 sequential LSTM steps */
#define E     1024
#define HH    1024
#define G4    4096
#define RULED 32
#define OUTD  2
#define NCTA  128
#define POISON 0xFFFFFFFFu   /* NaN bit pattern; h = o*tanh(c) in (-1,1) never matches */

/* Static device scratch — 256B-aligned so vector (128-bit) accesses are legal */
__device__ __align__(256) float g_X [(size_t)SEQ * E];        /* ~100 MB */
__device__ __align__(256) float g_Gx[(size_t)SEQ * G4];       /* ~403 MB */
__device__ __align__(256) float g_h [(size_t)(SEQ + 1) * HH]; /* ~100 MB */

/* ---- packed f32x2 helpers (sm_103a FFMA2 is PTX-only) ------------- */
__device__ __forceinline__ unsigned long long pk2(float x, float y) {
    unsigned long long r;
    asm("mov.b64 %0,{%1,%2};" : "=l"(r) : "f"(x), "f"(y));
    return r;
}
__device__ __forceinline__ unsigned long long fma2(
    unsigned long long a, unsigned long long b, unsigned long long c) {
    unsigned long long d;
    asm("fma.rn.f32x2 %0,%1,%2,%3;" : "=l"(d) : "l"(a), "l"(b), "l"(c));
    return d;
}
__device__ __forceinline__ float sum2(unsigned long long v) {
    float x, y;
    asm("mov.b64 {%0,%1},%2;" : "=f"(x), "=f"(y) : "l"(v));
    return x + y;
}

/* ------------------------------------------------------------------ */
/* Init: h row 0 = 0.0f, rows 1..SEQ = NaN poison (data IS the flag). */
__global__ __launch_bounds__(256) void poison_k()
{
    const size_t total = (size_t)(SEQ + 1) * HH;
    unsigned* p = (unsigned*)g_h;
    for (size_t i = (size_t)blockIdx.x * 256 + threadIdx.x; i < total;
         i += (size_t)gridDim.x * 256)
        p[i] = (i < HH) ? 0u : POISON;
}

/* ------------------------------------------------------------------ */
/* Build X: row 3n = rules@W_rule + b_rule, rows 3n+1/2 = face gather */
__global__ __launch_bounds__(256) void build_x_k(
    const float* __restrict__ rules, const int* __restrict__ id1,
    const int* __restrict__ id2, const float* __restrict__ W_rule,
    const float* __restrict__ b_rule, const float* __restrict__ face)
{
    int s = blockIdx.x;
    int n = s / 3, t = s - n * 3;
    float* dst = g_X + (size_t)s * E;
    if (t == 0) {
        __shared__ float r[RULED];
        if (threadIdx.x < RULED) r[threadIdx.x] = rules[n * RULED + threadIdx.x];
        __syncthreads();
        for (int e = threadIdx.x; e < E; e += 256) {
            float acc = b_rule[e];
            #pragma unroll
            for (int k = 0; k < RULED; ++k) acc += r[k] * W_rule[k * E + e];
            dst[e] = acc;
        }
    } else {
        int id = (t == 1 ? id1 : id2)[n];
        const float4* src = (const float4*)(face + (size_t)id * E);
        float4* d4 = (float4*)dst;
        for (int i = threadIdx.x; i < E / 4; i += 256) d4[i] = src[i];
    }
}

/* ------------------------------------------------------------------ */
/* Gx[s][r] = dot(X[s,:], W_ih[r,:]) + b_ih[r] + b_hh[r]  (C = A B^T) */
#define BM 128
#define BN 128
#define BK 16
__global__ __launch_bounds__(256) void gemm_gx_k(
    const float* __restrict__ B,          /* W_ih [4096][1024] */
    const float* __restrict__ bih, const float* __restrict__ bhh)
{
    __shared__ float As[BK][BM + 4];
    __shared__ float Bs[BK][BN + 4];
    const int bm = blockIdx.y * BM;
    const int bn = blockIdx.x * BN;
    const int tid = threadIdx.x;
    const int ty = tid >> 4, tx = tid & 15;
    float acc[8][8] = {};
    const float* A = g_X;

    for (int k0 = 0; k0 < E; k0 += BK) {
        #pragma unroll
        for (int v = 0; v < 2; ++v) {
            int f4  = tid * 2 + v;
            int row = f4 >> 2;
            int kq  = f4 & 3;
            float4 a = *(const float4*)(A + (size_t)(bm + row) * E + k0 + kq * 4);
            As[kq*4+0][row] = a.x; As[kq*4+1][row] = a.y;
            As[kq*4+2][row] = a.z; As[kq*4+3][row] = a.w;
            float4 b = *(const float4*)(B + (size_t)(bn + row) * E + k0 + kq * 4);
            Bs[kq*4+0][row] = b.x; Bs[kq*4+1][row] = b.y;
            Bs[kq*4+2][row] = b.z; Bs[kq*4+3][row] = b.w;
        }
        __syncthreads();
        #pragma unroll
        for (int k = 0; k < BK; ++k) {
            float ar[8], br[8];
            #pragma unroll
            for (int i = 0; i < 8; ++i) ar[i] = As[k][ty*8 + i];
            #pragma unroll
            for (int i = 0; i < 8; ++i) br[i] = Bs[k][tx*8 + i];
            #pragma unroll
            for (int i = 0; i < 8; ++i)
                #pragma unroll
                for (int j = 0; j < 8; ++j) acc[i][j] += ar[i] * br[j];
        }
        __syncthreads();
    }
    #pragma unroll
    for (int i = 0; i < 8; ++i) {
        size_t row = (size_t)(bm + ty*8 + i);
        #pragma unroll
        for (int j = 0; j < 8; ++j) {
            int col = bn + tx*8 + j;
            g_Gx[row * G4 + col] = acc[i][j] + bih[col] + bhh[col];
        }
    }
}

/* ------------------------------------------------------------------ */
/* Persistent sequential LSTM. 128 CTAs x 256 threads, 1 CTA/SM.      */
/* Round-5 skeleton (smem-staged h, one barrier) + f32x2 packed dot   */
/* + nanosleep poll backoff + all-lane redundant activations.         */
/* Warp w of CTA b owns h[j], j = b*8 + w.                            */
/* Dot layout: thread (warp,lane) covers k-pairs {64*i + 2*lane}.     */
__global__ __launch_bounds__(256, 1) void lstm_seq_k(const float* __restrict__ Whh)
{
    const int b    = blockIdx.x;
    const int tid  = threadIdx.x;
    const int warp = tid >> 5;
    const int lane = tid & 31;
    const int j    = b * 8 + warp;

    /* Packed weights: w2[q][i] = (Whh[q*HH+j][64i+2lane], ...[64i+2lane+1])
       Exactly 128 64-bit regs — same budget as round 5, no spill.     */
    unsigned long long w2[4][16];
    #pragma unroll
    for (int q = 0; q < 4; ++q) {
        const float* wr = Whh + (size_t)(q * HH + j) * HH;
        #pragma unroll
        for (int i = 0; i < 16; ++i) {
            float2 wf = *(const float2*)(wr + i * 64 + lane * 2);
            w2[q][i] = pk2(wf.x, wf.y);
        }
    }

    __shared__ __align__(16) float hs[2][HH];   /* double buffer */
    float c = 0.0f;

    for (int t = 0; t < SEQ; ++t) {
        /* gate-bias prefetch (independent of h; overlaps the poll) */
        const float* gx = g_Gx + (size_t)t * G4 + j;
        float gq0 = __ldg(gx);
        float gq1 = __ldg(gx + HH);
        float gq2 = __ldg(gx + 2 * HH);
        float gq3 = __ldg(gx + 3 * HH);

        /* poll own 4 words of h(t); nanosleep backoff keeps L2 clear */
        volatile const unsigned* src =
            (const unsigned*)g_h + (size_t)t * HH + 4 * tid;
        unsigned u0 = src[0], u1 = src[1], u2 = src[2], u3 = src[3];
        while (u0 == POISON || u1 == POISON || u2 == POISON || u3 == POISON) {
            __nanosleep(64);
            u0 = src[0]; u1 = src[1]; u2 = src[2]; u3 = src[3];
        }

        const int p = t & 1;
        *(float4*)&hs[p][4 * tid] =
            make_float4(__uint_as_float(u0), __uint_as_float(u1),
                        __uint_as_float(u2), __uint_as_float(u3));
        __syncthreads();

        /* packed dot: 4 gates x 16 k-pairs, h from smem (LDS.64) */
        unsigned long long acc0 = 0ull, acc1 = 0ull, acc2 = 0ull, acc3 = 0ull;
        #pragma unroll
        for (int i = 0; i < 16; ++i) {
            unsigned long long hp =
                *(const unsigned long long*)&hs[p][i * 64 + lane * 2];
            acc0 = fma2(w2[0][i], hp, acc0);
            acc1 = fma2(w2[1][i], hp, acc1);
            acc2 = fma2(w2[2][i], hp, acc2);
            acc3 = fma2(w2[3][i], hp, acc3);
        }
        float a0 = sum2(acc0), a1 = sum2(acc1), a2 = sum2(acc2), a3 = sum2(acc3);

        /* butterfly: every lane ends with all 4 full sums */
        #pragma unroll
        for (int off = 16; off; off >>= 1) {
            a0 += __shfl_xor_sync(0xffffffffu, a0, off);
            a1 += __shfl_xor_sync(0xffffffffu, a1, off);
            a2 += __shfl_xor_sync(0xffffffffu, a2, off);
            a3 += __shfl_xor_sync(0xffffffffu, a3, off);
        }

        /* all lanes compute activations redundantly (no broadcasts)   */
        /* sigmoid(x) = 0.5 + 0.5*tanh(x/2)  -> MUFU.TANH              */
        float ig = 0.5f + 0.5f * __tanhf(0.5f * (a0 + gq0));
        float fg = 0.5f + 0.5f * __tanhf(0.5f * (a1 + gq1));
        float gg = __tanhf(a2 + gq2);
        float og = 0.5f + 0.5f * __tanhf(0.5f * (a3 + gq3));

        c = fg * c + ig * gg;
        float hn = og * __tanhf(c);

        /* publish h(t+1): the stored value is itself the ready flag */
        if (lane == 0)
            __stcg(g_h + (size_t)(t + 1) * HH + j, hn);
    }
}

/* ------------------------------------------------------------------ */
/* out[n] = h(after sample n) @ W_out + b_out                          */
__global__ __launch_bounds__(256) void out_k(
    const float* __restrict__ Wout, const float* __restrict__ bout,
    float* __restrict__ out)
{
    int n = blockIdx.x;
    const float* h = g_h + (size_t)(3 * n + 3) * HH;
    float p0 = 0.f, p1 = 0.f;
    for (int jj = threadIdx.x; jj < HH; jj += 256) {
        float hv = h[jj];
        p0 += hv * Wout[jj * 2 + 0];
        p1 += hv * Wout[jj * 2 + 1];
    }
    __shared__ float s0[256], s1[256];
    s0[threadIdx.x] = p0; s1[threadIdx.x] = p1;
    __syncthreads();
    for (int st = 128; st; st >>= 1) {
        if (threadIdx.x < st) {
            s0[threadIdx.x] += s0[threadIdx.x + st];
            s1[threadIdx.x] += s1[threadIdx.x + st];
        }
        __syncthreads();
    }
    if (threadIdx.x == 0) {
        out[n * 2 + 0] = s0[0] + bout[0];
        out[n * 2 + 1] = s1[0] + bout[1];
    }
}

/* ------------------------------------------------------------------ */
extern "C" void kernel_launch(void* const* d_in, const int* in_sizes, int n_in,
                              void* d_out, int out_size)
{
    const float* rules  = (const float*)d_in[0];
    const int*   id1    = (const int*)  d_in[1];
    const int*   id2    = (const int*)  d_in[2];
    const float* W_rule = (const float*)d_in[3];
    const float* b_rule = (const float*)d_in[4];
    const float* face   = (const float*)d_in[5];
    const float* W_ih   = (const float*)d_in[6];
    const float* W_hh   = (const float*)d_in[7];
    const float* b_ih   = (const float*)d_in[8];
    const float* b_hh   = (const float*)d_in[9];
    const float* W_out  = (const float*)d_in[10];
    const float* b_out  = (const float*)d_in[11];
    float* out = (float*)d_out;

    poison_k<<<2048, 256>>>();
    build_x_k<<<SEQ, 256>>>(rules, id1, id2, W_rule, b_rule, face);
    gemm_gx_k<<<dim3(G4 / BN, SEQ / BM), 256>>>(W_ih, b_ih, b_hh);
    lstm_seq_k<<<NCTA, 256>>>(W_hh);
    out_k<<<NSAMP, 256>>>(W_out, b_out, out);
}